// round 1
// baseline (speedup 1.0000x reference)
#include <cuda_runtime.h>
#include <math.h>
#include <float.h>

// Problem constants
#define Bc    2
#define Sc    1024
#define HIDc  2048
#define NHc   16
#define HDc   128
#define SBc   20     // stream budget
#define RBc   82     // recent budget
#define CBc   163    // cache budget (20+61+82)
#define FFc   0.9f

#define BSc   (Bc*Sc)          // 2048
#define ZB    (Bc*NHc)         // 32 batched heads

// ----------------------------------------------------------------------------
// Scratch (static __device__ arrays; no allocation allowed)
// ----------------------------------------------------------------------------
__device__ float g_Qlin[Bc*Sc*HIDc];
__device__ float g_Klin[Bc*Sc*HIDc];
__device__ float g_Vlin[Bc*Sc*HIDc];
__device__ float g_Q[ZB*Sc*HDc];
__device__ float g_K[ZB*Sc*HDc];
__device__ float g_V[ZB*Sc*HDc];
__device__ float g_P[(size_t)ZB*Sc*Sc];   // 128 MB: logits -> scores -> masked probs
__device__ float g_ctx[Bc*Sc*HIDc];
__device__ int   g_evict[ZB*Sc];

// ----------------------------------------------------------------------------
// Generic fp32 tiled GEMM: C = alpha * A @ B(^T), 128x128x16 tiles, 256 thr
// Batched via blockIdx.z. C batch offset = (z/nhdiv)*sCo + (z%nhdiv)*sCi.
// CAUSAL epilogue: col > row -> -FLT_MAX (matches maximum(attn+causal, min)).
// ----------------------------------------------------------------------------
template<bool TRANSB, bool CAUSAL>
__global__ void __launch_bounds__(256) gemm128(
    const float* __restrict__ A, const float* __restrict__ Bm, float* __restrict__ C,
    int M, int N, int K, int lda, int ldb, int ldc,
    long long sA, long long sB, long long sCo, long long sCi, int nhdiv,
    float alpha)
{
    int z = blockIdx.z;
    A  += (long long)z * sA;
    Bm += (long long)z * sB;
    C  += (long long)(z / nhdiv) * sCo + (long long)(z % nhdiv) * sCi;

    __shared__ float As[16][132];
    __shared__ float Bs[16][132];

    const int tid = threadIdx.x;
    const int m0 = blockIdx.y * 128;
    const int n0 = blockIdx.x * 128;
    const int ty = tid >> 4;       // 0..15
    const int tx = tid & 15;       // 0..15

    float acc[8][8];
#pragma unroll
    for (int i = 0; i < 8; i++)
#pragma unroll
        for (int j = 0; j < 8; j++) acc[i][j] = 0.f;

    for (int k0 = 0; k0 < K; k0 += 16) {
        // Load A tile transposed: As[k][m] = A[m0+m][k0+k]
#pragma unroll
        for (int i = 0; i < 2; i++) {
            int slot = tid * 2 + i;          // 0..511
            int m  = slot >> 2;
            int kq = (slot & 3) * 4;
            float4 v = *(const float4*)&A[(long long)(m0 + m) * lda + k0 + kq];
            As[kq + 0][m] = v.x; As[kq + 1][m] = v.y;
            As[kq + 2][m] = v.z; As[kq + 3][m] = v.w;
        }
        if (TRANSB) {
            // B given as [N x K] row-major; Bs[k][n] = Bm[n0+n][k0+k]
#pragma unroll
            for (int i = 0; i < 2; i++) {
                int slot = tid * 2 + i;
                int n  = slot >> 2;
                int kq = (slot & 3) * 4;
                float4 v = *(const float4*)&Bm[(long long)(n0 + n) * ldb + k0 + kq];
                Bs[kq + 0][n] = v.x; Bs[kq + 1][n] = v.y;
                Bs[kq + 2][n] = v.z; Bs[kq + 3][n] = v.w;
            }
        } else {
            // B given as [K x N] row-major; Bs[k][n] = Bm[k0+k][n0+n]
#pragma unroll
            for (int i = 0; i < 2; i++) {
                int slot = tid * 2 + i;      // 0..511 = 16 rows x 32 quads
                int kk = slot >> 5;
                int nq = (slot & 31) * 4;
                float4 v = *(const float4*)&Bm[(long long)(k0 + kk) * ldb + n0 + nq];
                *(float4*)&Bs[kk][nq] = v;
            }
        }
        __syncthreads();

#pragma unroll
        for (int kk = 0; kk < 16; kk++) {
            float a[8], b[8];
            *(float4*)&a[0] = *(const float4*)&As[kk][ty * 8];
            *(float4*)&a[4] = *(const float4*)&As[kk][ty * 8 + 4];
            *(float4*)&b[0] = *(const float4*)&Bs[kk][tx * 8];
            *(float4*)&b[4] = *(const float4*)&Bs[kk][tx * 8 + 4];
#pragma unroll
            for (int i = 0; i < 8; i++)
#pragma unroll
                for (int j = 0; j < 8; j++)
                    acc[i][j] += a[i] * b[j];
        }
        __syncthreads();
    }

#pragma unroll
    for (int i = 0; i < 8; i++) {
        int gm = m0 + ty * 8 + i;
#pragma unroll
        for (int j = 0; j < 8; j++) {
            int gn = n0 + tx * 8 + j;
            float v = acc[i][j] * alpha;
            if (CAUSAL && gn > gm) v = -FLT_MAX;
            C[(long long)gm * ldc + gn] = v;
        }
    }
}

// ----------------------------------------------------------------------------
// RoPE + layout transform: [B,S,H*D] -> [B,H,S,D] (V: transform only)
// ----------------------------------------------------------------------------
__global__ void rope_kernel()
{
    __shared__ float invf_s[64];
    if (threadIdx.x < 64)
        invf_s[threadIdx.x] = (float)pow(10000.0, -(double)threadIdx.x / 64.0);
    __syncthreads();

    long long idx = (long long)blockIdx.x * blockDim.x + threadIdx.x;
    if (idx >= (long long)Bc * Sc * HIDc) return;

    int d = (int)(idx % HDc);
    int h = (int)((idx / HDc) % NHc);
    int s = (int)((idx / HIDc) % Sc);
    int b = (int)(idx / ((long long)Sc * HIDc));

    long long lin = (long long)(b * Sc + s) * HIDc + h * HDc + d;
    long long out = (long long)((b * NHc + h) * Sc + s) * HDc + d;

    float q = g_Qlin[lin];
    float k = g_Klin[lin];
    float qr, kr;
    if (d < 64) { qr = -g_Qlin[lin + 64]; kr = -g_Klin[lin + 64]; }
    else        { qr =  g_Qlin[lin - 64]; kr =  g_Klin[lin - 64]; }

    float ang = (float)s * invf_s[d & 63];
    float c = cosf(ang), sn = sinf(ang);

    g_Q[out] = q * c + qr * sn;
    g_K[out] = k * c + kr * sn;
    g_V[out] = g_Vlin[lin];
}

// ----------------------------------------------------------------------------
// Row softmax over P (rows of length 1024), one 256-thread block per row
// ----------------------------------------------------------------------------
__global__ void __launch_bounds__(256) softmax_rows(float* __restrict__ P)
{
    __shared__ float smA[9];
    __shared__ float smB[9];
    long long row = blockIdx.x;
    float* p = P + row * Sc;
    const int tid = threadIdx.x;
    const int lane = tid & 31, wid = tid >> 5;

    float v[4];
    float mx = -FLT_MAX;
#pragma unroll
    for (int i = 0; i < 4; i++) { v[i] = p[tid + i * 256]; mx = fmaxf(mx, v[i]); }
#pragma unroll
    for (int o = 16; o; o >>= 1) mx = fmaxf(mx, __shfl_xor_sync(0xffffffffu, mx, o));
    if (lane == 0) smA[wid] = mx;
    __syncthreads();
    if (tid < 8) {
        float x = smA[tid];
#pragma unroll
        for (int o = 4; o; o >>= 1) x = fmaxf(x, __shfl_xor_sync(0xffu, x, o));
        if (tid == 0) smA[8] = x;
    }
    __syncthreads();
    mx = smA[8];

    float sum = 0.f;
#pragma unroll
    for (int i = 0; i < 4; i++) { v[i] = expf(v[i] - mx); sum += v[i]; }
#pragma unroll
    for (int o = 16; o; o >>= 1) sum += __shfl_xor_sync(0xffffffffu, sum, o);
    if (lane == 0) smB[wid] = sum;
    __syncthreads();
    if (tid < 8) {
        float x = smB[tid];
#pragma unroll
        for (int o = 4; o; o >>= 1) x += __shfl_xor_sync(0xffu, x, o);
        if (tid == 0) smB[8] = x;
    }
    __syncthreads();
    sum = smB[8];

    float inv = 1.f / sum;
#pragma unroll
    for (int i = 0; i < 4; i++) p[tid + i * 256] = v[i] * inv;
}

// ----------------------------------------------------------------------------
// Sequential heavy-hitter eviction scan. One 1024-thread block per (b,h).
// Thread j owns position j: sel lives in a register, mask = (sel < inf).
// Records eviction step e[j] (INT_MAX if never evicted).
// keep[r][j] = (r <= CB) || (e[j] >= r)
// ----------------------------------------------------------------------------
__global__ void __launch_bounds__(1024) scan_kernel(const float* __restrict__ P,
                                                    int* __restrict__ evict)
{
    const int z = blockIdx.x;
    const float* Pz = P + (long long)z * Sc * Sc;
    const int j = threadIdx.x;
    const int lane = j & 31, wid = j >> 5;

    __shared__ float wcoef[CBc];
    __shared__ float sred[33];
    __shared__ unsigned long long mred[33];

    if (j < CBc) wcoef[j] = powf(FFc, (float)(CBc - 1 - j));
    __syncthreads();

    // EMA warmup over rows 0..CB-1
    float sel = 0.f;
    for (int i = 0; i < CBc; i++)
        sel += wcoef[i] * Pz[(long long)i * Sc + j];

    const float INFV = __int_as_float(0x7f800000);
    int my_e = 0x7fffffff;

    for (int t = CBc; t <= Sc - 2; t++) {
        float sc = __ldg(&Pz[(long long)t * Sc + j]);
        bool alive = (sel < INFV);
        float cur = alive ? sc : 0.f;

        // block sum of cur
        float x = cur;
#pragma unroll
        for (int o = 16; o; o >>= 1) x += __shfl_xor_sync(0xffffffffu, x, o);
        if (lane == 0) sred[wid] = x;
        __syncthreads();
        if (j < 32) {
            float y = sred[j];
#pragma unroll
            for (int o = 16; o; o >>= 1) y += __shfl_xor_sync(0xffffffffu, y, o);
            if (j == 0) sred[32] = y;
        }
        __syncthreads();
        float total = sred[32];

        sel = alive ? (FFc * sel + cur / total) : INFV;

        // windowed argmin (first index on ties): sel >= 0 so float bits are
        // order-preserving; key = (bits<<32)|j, u64 min.
        unsigned long long key = ~0ull;
        if (j >= SBc && j <= t - RBc)
            key = (((unsigned long long)__float_as_uint(sel)) << 32) | (unsigned)j;
#pragma unroll
        for (int o = 16; o; o >>= 1) {
            unsigned long long other = __shfl_xor_sync(0xffffffffu, key, o);
            key = (other < key) ? other : key;
        }
        if (lane == 0) mred[wid] = key;
        __syncthreads();
        if (j < 32) {
            unsigned long long y = mred[j];
#pragma unroll
            for (int o = 16; o; o >>= 1) {
                unsigned long long other = __shfl_xor_sync(0xffffffffu, y, o);
                y = (other < y) ? other : y;
            }
            if (j == 0) mred[32] = y;
        }
        __syncthreads();
        int mi = (int)(mred[32] & 0xffffffffu);
        if (j == mi) { sel = INFV; my_e = t; }
        // no trailing barrier needed: next writes to sred/mred are separated
        // from this iteration's reads by two __syncthreads each.
    }

    evict[z * Sc + j] = my_e;
}

// ----------------------------------------------------------------------------
// Apply keep-mask and renormalize rows of P in place (one block per row)
// ----------------------------------------------------------------------------
__global__ void __launch_bounds__(256) maskrenorm(float* __restrict__ P,
                                                  const int* __restrict__ evict)
{
    __shared__ float smB[9];
    long long row = blockIdx.x;
    int z = (int)(row >> 10);
    int r = (int)(row & 1023);
    float* p = P + row * Sc;
    const int* e = evict + z * Sc;
    const int tid = threadIdx.x;
    const int lane = tid & 31, wid = tid >> 5;

    float v[4];
    float sum = 0.f;
#pragma unroll
    for (int i = 0; i < 4; i++) {
        int jj = tid + i * 256;
        bool keep = (r <= CBc) || (e[jj] >= r);
        v[i] = keep ? p[jj] : 0.f;
        sum += v[i];
    }
#pragma unroll
    for (int o = 16; o; o >>= 1) sum += __shfl_xor_sync(0xffffffffu, sum, o);
    if (lane == 0) smB[wid] = sum;
    __syncthreads();
    if (tid < 8) {
        float x = smB[tid];
#pragma unroll
        for (int o = 4; o; o >>= 1) x += __shfl_xor_sync(0xffu, x, o);
        if (tid == 0) smB[8] = x;
    }
    __syncthreads();
    sum = smB[8];

    float inv = 1.f / sum;
#pragma unroll
    for (int i = 0; i < 4; i++) p[tid + i * 256] = v[i] * inv;
}

// ----------------------------------------------------------------------------
// Launch
// ----------------------------------------------------------------------------
extern "C" void kernel_launch(void* const* d_in, const int* in_sizes, int n_in,
                              void* d_out, int out_size)
{
    (void)in_sizes; (void)n_in; (void)out_size;
    const float* hs = (const float*)d_in[0];
    const float* wq = (const float*)d_in[1];
    const float* wk = (const float*)d_in[2];
    const float* wv = (const float*)d_in[3];
    const float* wo = (const float*)d_in[4];
    float* out = (float*)d_out;

    float *Qlin, *Klin, *Vlin, *Q, *K, *V, *P, *ctx;
    int* ev;
    cudaGetSymbolAddress((void**)&Qlin, g_Qlin);
    cudaGetSymbolAddress((void**)&Klin, g_Klin);
    cudaGetSymbolAddress((void**)&Vlin, g_Vlin);
    cudaGetSymbolAddress((void**)&Q, g_Q);
    cudaGetSymbolAddress((void**)&K, g_K);
    cudaGetSymbolAddress((void**)&V, g_V);
    cudaGetSymbolAddress((void**)&P, g_P);
    cudaGetSymbolAddress((void**)&ctx, g_ctx);
    cudaGetSymbolAddress((void**)&ev, g_evict);

    const float qk_scale = (float)(1.0 / sqrt((double)HDc));

    // 1) QKV projections: [2048x2048] @ [2048x2048]
    dim3 gProj(HIDc / 128, BSc / 128, 1);
    gemm128<false, false><<<gProj, 256>>>(hs, wq, Qlin,
        BSc, HIDc, HIDc, HIDc, HIDc, HIDc, 0, 0, 0, 0, 1, 1.f);
    gemm128<false, false><<<gProj, 256>>>(hs, wk, Klin,
        BSc, HIDc, HIDc, HIDc, HIDc, HIDc, 0, 0, 0, 0, 1, 1.f);
    gemm128<false, false><<<gProj, 256>>>(hs, wv, Vlin,
        BSc, HIDc, HIDc, HIDc, HIDc, HIDc, 0, 0, 0, 0, 1, 1.f);

    // 2) RoPE + [B,H,S,D] layout
    {
        long long total = (long long)Bc * Sc * HIDc;
        rope_kernel<<<(unsigned)((total + 255) / 256), 256>>>();
    }

    // 3) Causal scaled QK^T per head: P = Q @ K^T * scale (masked -> -FLT_MAX)
    gemm128<true, true><<<dim3(Sc / 128, Sc / 128, ZB), 256>>>(Q, K, P,
        Sc, Sc, HDc, HDc, HDc, Sc,
        (long long)Sc * HDc, (long long)Sc * HDc,
        0, (long long)Sc * Sc, 1000000, qk_scale);

    // 4) Softmax -> scores
    softmax_rows<<<ZB * Sc, 256>>>(P);

    // 5) Sequential eviction scan (32 independent scans)
    scan_kernel<<<ZB, 1024>>>(P, ev);

    // 6) Keep-mask + renormalize in place
    maskrenorm<<<ZB * Sc, 256>>>(P, ev);

    // 7) PV: ctx[b,s,h*D+d] = sum_j P[z,s,j] * V[z,j,d]
    gemm128<false, false><<<dim3(1, Sc / 128, ZB), 256>>>(P, V, ctx,
        Sc, HDc, Sc, Sc, HDc, HIDc,
        (long long)Sc * Sc, (long long)Sc * HDc,
        (long long)Sc * HIDc, (long long)HDc, NHc, 1.f);

    // 8) Output projection
    gemm128<false, false><<<gProj, 256>>>(ctx, wo, out,
        BSc, HIDc, HIDc, HIDc, HIDc, HIDc, 0, 0, 0, 0, 1, 1.f);
}

// round 3
// speedup vs baseline: 1.7212x; 1.7212x over previous
#include <cuda_runtime.h>
#include <cuda_bf16.h>
#include <math.h>
#include <float.h>
#include <stdint.h>

// Problem constants
#define Bc    2
#define Sc    1024
#define HIDc  2048
#define NHc   16
#define HDc   128
#define SBc   20
#define RBc   82
#define CBc   163
#define FFc   0.9f
#define BSc   (Bc*Sc)          // 2048
#define ZB    (Bc*NHc)         // 32

// ----------------------------------------------------------------------------
// Scratch
// ----------------------------------------------------------------------------
__device__ __align__(1024) float g_Qlin[BSc*HIDc];
__device__ __align__(1024) float g_Klin[BSc*HIDc];
__device__ __align__(1024) float g_Vlin[BSc*HIDc];
__device__ __align__(1024) __nv_bfloat16 g_hsH[BSc*HIDc];
__device__ __align__(1024) __nv_bfloat16 g_hsL[BSc*HIDc];
__device__ __align__(1024) __nv_bfloat16 g_wqH[HIDc*HIDc];
__device__ __align__(1024) __nv_bfloat16 g_wqL[HIDc*HIDc];
__device__ __align__(1024) __nv_bfloat16 g_wkH[HIDc*HIDc];
__device__ __align__(1024) __nv_bfloat16 g_wkL[HIDc*HIDc];
__device__ __align__(1024) __nv_bfloat16 g_wvH[HIDc*HIDc];
__device__ __align__(1024) __nv_bfloat16 g_wvL[HIDc*HIDc];
__device__ __align__(1024) __nv_bfloat16 g_woH[HIDc*HIDc];
__device__ __align__(1024) __nv_bfloat16 g_woL[HIDc*HIDc];
__device__ __align__(1024) __nv_bfloat16 g_QH[ZB*Sc*HDc];
__device__ __align__(1024) __nv_bfloat16 g_QL[ZB*Sc*HDc];
__device__ __align__(1024) __nv_bfloat16 g_KH[ZB*Sc*HDc];
__device__ __align__(1024) __nv_bfloat16 g_KL[ZB*Sc*HDc];
__device__ __align__(1024) __nv_bfloat16 g_VH[ZB*Sc*HDc];
__device__ __align__(1024) __nv_bfloat16 g_VL[ZB*Sc*HDc];
__device__ __align__(1024) float g_P[(size_t)ZB*Sc*Sc];
__device__ __align__(1024) __nv_bfloat16 g_PH[(size_t)ZB*Sc*Sc];
__device__ __align__(1024) __nv_bfloat16 g_PL[(size_t)ZB*Sc*Sc];
__device__ __align__(1024) float g_ctx[BSc*HIDc];
__device__ __align__(1024) __nv_bfloat16 g_cH[BSc*HIDc];
__device__ __align__(1024) __nv_bfloat16 g_cL[BSc*HIDc];
__device__ int g_evict[ZB*Sc];

// ----------------------------------------------------------------------------
// PTX helpers (baseline PTX only: cp.async, ldmatrix, mma.sync — all sm_80+)
// ----------------------------------------------------------------------------
__device__ __forceinline__ uint32_t smem_u32(const void* p){
    uint32_t a;
    asm("{ .reg .u64 t; cvta.to.shared.u64 t, %1; cvt.u32.u64 %0, t; }":"=r"(a):"l"(p));
    return a;
}
__device__ __forceinline__ void cp16(uint32_t d, const void* s){
    asm volatile("cp.async.cg.shared.global [%0], [%1], 16;"::"r"(d),"l"(s));
}
#define CP_COMMIT() asm volatile("cp.async.commit_group;":::"memory")
#define CP_WAIT(n)  asm volatile("cp.async.wait_group %0;"::"n"(n):"memory")

__device__ __forceinline__ void ldsm4(uint32_t r[4], uint32_t a){
    asm volatile("ldmatrix.sync.aligned.m8n8.x4.shared.b16 {%0,%1,%2,%3}, [%4];"
        : "=r"(r[0]),"=r"(r[1]),"=r"(r[2]),"=r"(r[3]) : "r"(a));
}
__device__ __forceinline__ void ldsm4t(uint32_t r[4], uint32_t a){
    asm volatile("ldmatrix.sync.aligned.m8n8.x4.trans.shared.b16 {%0,%1,%2,%3}, [%4];"
        : "=r"(r[0]),"=r"(r[1]),"=r"(r[2]),"=r"(r[3]) : "r"(a));
}
__device__ __forceinline__ void mma16816(float d[4], const uint32_t a[4], const uint32_t b[2]){
    asm volatile("mma.sync.aligned.m16n8k16.row.col.f32.bf16.bf16.f32 "
        "{%0,%1,%2,%3},{%4,%5,%6,%7},{%8,%9},{%0,%1,%2,%3};"
        : "+f"(d[0]),"+f"(d[1]),"+f"(d[2]),"+f"(d[3])
        : "r"(a[0]),"r"(a[1]),"r"(a[2]),"r"(a[3]),"r"(b[0]),"r"(b[1]));
}

#define TILEB       16384
#define STAGE_BYTES 65536
#define GSMEM_TOTAL 131072

// Copy a [128 rows x 64 bf16] tile, rowbytes=128, XOR-(r&7) chunk swizzle.
__device__ __forceinline__ void copy_rk(uint32_t dst, const __nv_bfloat16* src,
                                        int ld, int tid){
#pragma unroll
    for (int i=0;i<4;i++){
        int idx = tid + i*256;
        int r = idx>>3, c = idx&7;
        uint32_t sw = (uint32_t)(r*128) + (uint32_t)(((c ^ (r&7))<<4));
        cp16(dst + sw, (const char*)src + ((long long)r*ld + c*8)*2);
    }
}
// Copy a [64 rows(k) x 128 bf16(n)] tile, rowbytes=256, XOR-(r&7) chunk swizzle.
__device__ __forceinline__ void copy_kn(uint32_t dst, const __nv_bfloat16* src,
                                        int ld, int tid){
#pragma unroll
    for (int i=0;i<4;i++){
        int idx = tid + i*256;
        int r = idx>>4, c = idx&15;
        uint32_t sw = (uint32_t)(r*256) + (uint32_t)(((c ^ (r&7))<<4));
        cp16(dst + sw, (const char*)src + ((long long)r*ld + c*8)*2);
    }
}

// ----------------------------------------------------------------------------
// HMMA GEMM: C[M,N] = alpha * (Ah+Al)[M,K] @ (Bh+Bl)^T, fp32 C, 3-term split.
// BKN=true : B stored [K,N] row-major (trans ldmatrix)
// BKN=false: B stored [N,K] row-major
// CAUSAL: skip 128x128 blocks strictly above the diagonal.
// CTA 128x128, 8 warps (2x4 of 64x32), K-chunk 64, 2-stage cp.async pipeline.
// ----------------------------------------------------------------------------
template<bool BKN, bool CAUSAL>
__global__ void __launch_bounds__(256) gemm_mma(
    const __nv_bfloat16* __restrict__ Ah, const __nv_bfloat16* __restrict__ Al,
    const __nv_bfloat16* __restrict__ Bh, const __nv_bfloat16* __restrict__ Bl,
    float* __restrict__ C, int K, int ldb, int ldc,
    long long sA, long long sB, long long sCo, long long sCi, int ndiv, float alpha)
{
    const int m0 = blockIdx.y*128, n0 = blockIdx.x*128, z = blockIdx.z;
    if (CAUSAL && n0 > m0) return;
    extern __shared__ __align__(1024) char smem[];
    const uint32_t sb = smem_u32(smem);
    Ah += (long long)z*sA; Al += (long long)z*sA;
    Bh += (long long)z*sB; Bl += (long long)z*sB;
    C  += (long long)(z/ndiv)*sCo + (long long)(z%ndiv)*sCi;

    const int tid = threadIdx.x, lane = tid&31, wid = tid>>5;
    const int wm = wid>>2, wn = wid&3;

    float acc[4][4][4];
#pragma unroll
    for (int a=0;a<4;a++)
#pragma unroll
        for (int b=0;b<4;b++)
#pragma unroll
            for (int c=0;c<4;c++) acc[a][b][c] = 0.f;

    const int nch = K>>6;

#define LOAD_CHUNK(cc, ss) do{ \
    uint32_t bbase = sb + (uint32_t)(ss)*STAGE_BYTES; \
    copy_rk(bbase,           Ah + (long long)m0*K + (cc)*64, K, tid); \
    copy_rk(bbase + TILEB,   Al + (long long)m0*K + (cc)*64, K, tid); \
    if (BKN){ \
        copy_kn(bbase + 2*TILEB, Bh + (long long)(cc)*64*ldb + n0, ldb, tid); \
        copy_kn(bbase + 3*TILEB, Bl + (long long)(cc)*64*ldb + n0, ldb, tid); \
    } else { \
        copy_rk(bbase + 2*TILEB, Bh + (long long)n0*K + (cc)*64, K, tid); \
        copy_rk(bbase + 3*TILEB, Bl + (long long)n0*K + (cc)*64, K, tid); \
    } \
    CP_COMMIT(); }while(0)

    LOAD_CHUNK(0, 0);
    if (nch > 1) LOAD_CHUNK(1, 1);

    const uint32_t axor = (uint32_t)(lane&7);

    for (int c=0; c<nch; c++){
        if (c+1 < nch) CP_WAIT(1); else CP_WAIT(0);
        __syncthreads();
        uint32_t base = sb + (uint32_t)(c&1)*STAGE_BYTES;
#pragma unroll
        for (int ks=0; ks<4; ks++){
            uint32_t ah[4][4], al[4][4], bh[4][2], bl[4][2];
#pragma unroll
            for (int mb=0;mb<4;mb++){
                uint32_t row = (uint32_t)(wm*64 + mb*16 + (lane&15));
                uint32_t col = (((uint32_t)(ks*2 + (lane>>4)) ^ axor)<<4);
                uint32_t ad = base + row*128 + col;
                ldsm4(ah[mb], ad);
                ldsm4(al[mb], ad + TILEB);
            }
#pragma unroll
            for (int nb=0;nb<2;nb++){
                uint32_t t[4];
                if (BKN){
                    uint32_t row = (uint32_t)(ks*16 + (lane&7) + (((lane>>3)&1)<<3));
                    uint32_t ch  = ((uint32_t)(wn*4 + nb*2 + (lane>>4)) ^ axor);
                    uint32_t ad  = base + 2*TILEB + row*256 + (ch<<4);
                    ldsm4t(t, ad);
                    bh[2*nb][0]=t[0]; bh[2*nb][1]=t[1]; bh[2*nb+1][0]=t[2]; bh[2*nb+1][1]=t[3];
                    ldsm4t(t, ad + TILEB);
                    bl[2*nb][0]=t[0]; bl[2*nb][1]=t[1]; bl[2*nb+1][0]=t[2]; bl[2*nb+1][1]=t[3];
                } else {
                    uint32_t row = (uint32_t)(wn*32 + nb*16 + (lane&7) + ((lane>>4)<<3));
                    uint32_t ch  = ((uint32_t)(ks*2 + ((lane>>3)&1)) ^ axor);
                    uint32_t ad  = base + 2*TILEB + row*128 + (ch<<4);
                    ldsm4(t, ad);
                    bh[2*nb][0]=t[0]; bh[2*nb][1]=t[1]; bh[2*nb+1][0]=t[2]; bh[2*nb+1][1]=t[3];
                    ldsm4(t, ad + TILEB);
                    bl[2*nb][0]=t[0]; bl[2*nb][1]=t[1]; bl[2*nb+1][0]=t[2]; bl[2*nb+1][1]=t[3];
                }
            }
#pragma unroll
            for (int mb=0;mb<4;mb++)
#pragma unroll
                for (int n8=0;n8<4;n8++){
                    mma16816(acc[mb][n8], ah[mb], bh[n8]);
                    mma16816(acc[mb][n8], ah[mb], bl[n8]);
                    mma16816(acc[mb][n8], al[mb], bh[n8]);
                }
        }
        __syncthreads();
        if (c+2 < nch) LOAD_CHUNK(c+2, c&1);
    }
#undef LOAD_CHUNK

    // epilogue
#pragma unroll
    for (int mb=0;mb<4;mb++){
        int r0 = m0 + wm*64 + mb*16 + (lane>>2);
#pragma unroll
        for (int n8=0;n8<4;n8++){
            int cc = n0 + wn*32 + n8*8 + (lane&3)*2;
            float2 v0; v0.x = acc[mb][n8][0]*alpha; v0.y = acc[mb][n8][1]*alpha;
            float2 v1; v1.x = acc[mb][n8][2]*alpha; v1.y = acc[mb][n8][3]*alpha;
            *(float2*)&C[(long long)r0*ldc + cc] = v0;
            *(float2*)&C[(long long)(r0+8)*ldc + cc] = v1;
        }
    }
}

// ----------------------------------------------------------------------------
// fp32 -> bf16 hi/lo split (same layout), 4 elems/thread
// ----------------------------------------------------------------------------
__global__ void split_plain(const float* __restrict__ X,
                            __nv_bfloat16* __restrict__ H,
                            __nv_bfloat16* __restrict__ L, int n)
{
    int i = (blockIdx.x*blockDim.x + threadIdx.x)*4;
    if (i < n){
        float4 v = *(const float4*)&X[i];
        __nv_bfloat16 h0=__float2bfloat16(v.x), h1=__float2bfloat16(v.y);
        __nv_bfloat16 h2=__float2bfloat16(v.z), h3=__float2bfloat16(v.w);
        __nv_bfloat162 H01; H01.x=h0; H01.y=h1;
        __nv_bfloat162 H23; H23.x=h2; H23.y=h3;
        *(__nv_bfloat162*)&H[i]   = H01;
        *(__nv_bfloat162*)&H[i+2] = H23;
        __nv_bfloat162 L01, L23;
        L01.x = __float2bfloat16(v.x - __bfloat162float(h0));
        L01.y = __float2bfloat16(v.y - __bfloat162float(h1));
        L23.x = __float2bfloat16(v.z - __bfloat162float(h2));
        L23.y = __float2bfloat16(v.w - __bfloat162float(h3));
        *(__nv_bfloat162*)&L[i]   = L01;
        *(__nv_bfloat162*)&L[i+2] = L23;
    }
}

// ----------------------------------------------------------------------------
// RoPE + [B,S,H*D]->[Z,S,D] layout + bf16 hi/lo split (all coalesced)
// ----------------------------------------------------------------------------
__global__ void rope_split()
{
    __shared__ float invf_s[64];
    if (threadIdx.x < 64)
        invf_s[threadIdx.x] = (float)pow(10000.0, -(double)threadIdx.x / 64.0);
    __syncthreads();

    long long idx = (long long)blockIdx.x * blockDim.x + threadIdx.x;
    if (idx >= (long long)Bc * Sc * HIDc) return;

    int d = (int)(idx % HDc);
    int h = (int)((idx / HDc) % NHc);
    int s = (int)((idx / HIDc) % Sc);
    int b = (int)(idx / ((long long)Sc * HIDc));
    int z = b*NHc + h;

    long long lin = (long long)(b * Sc + s) * HIDc + h * HDc + d;
    long long out = (long long)(z * Sc + s) * HDc + d;

    float q = g_Qlin[lin];
    float k = g_Klin[lin];
    float qr, kr;
    if (d < 64) { qr = -g_Qlin[lin + 64]; kr = -g_Klin[lin + 64]; }
    else        { qr =  g_Qlin[lin - 64]; kr =  g_Klin[lin - 64]; }

    float ang = (float)s * invf_s[d & 63];
    float c = cosf(ang), sn = sinf(ang);

    float qv = q * c + qr * sn;
    float kv = k * c + kr * sn;

    __nv_bfloat16 qh = __float2bfloat16(qv);
    g_QH[out] = qh; g_QL[out] = __float2bfloat16(qv - __bfloat162float(qh));
    __nv_bfloat16 kh = __float2bfloat16(kv);
    g_KH[out] = kh; g_KL[out] = __float2bfloat16(kv - __bfloat162float(kh));

    float vv = g_Vlin[lin];
    __nv_bfloat16 vh = __float2bfloat16(vv);
    g_VH[out] = vh; g_VL[out] = __float2bfloat16(vv - __bfloat162float(vh));
}

// ----------------------------------------------------------------------------
// Causal row softmax: row r uses j<=r; writes 0 above the diagonal
// ----------------------------------------------------------------------------
__global__ void __launch_bounds__(256) softmax_causal(float* __restrict__ P)
{
    __shared__ float smA[9];
    __shared__ float smB[9];
    long long row = blockIdx.x;
    int r = (int)(row & (Sc-1));
    float* p = P + row * Sc;
    const int tid = threadIdx.x;
    const int lane = tid & 31, wid = tid >> 5;

    float v[4];
    float mx = -FLT_MAX;
#pragma unroll
    for (int i = 0; i < 4; i++) {
        int jj = tid + i*256;
        v[i] = (jj <= r) ? p[jj] : -FLT_MAX;
        mx = fmaxf(mx, v[i]);
    }
#pragma unroll
    for (int o = 16; o; o >>= 1) mx = fmaxf(mx, __shfl_xor_sync(0xffffffffu, mx, o));
    if (lane == 0) smA[wid] = mx;
    __syncthreads();
    if (tid < 8) {
        float x = smA[tid];
#pragma unroll
        for (int o = 4; o; o >>= 1) x = fmaxf(x, __shfl_xor_sync(0xffu, x, o));
        if (tid == 0) smA[8] = x;
    }
    __syncthreads();
    mx = smA[8];

    float sum = 0.f;
#pragma unroll
    for (int i = 0; i < 4; i++) { v[i] = expf(v[i] - mx); sum += v[i]; }
#pragma unroll
    for (int o = 16; o; o >>= 1) sum += __shfl_xor_sync(0xffffffffu, sum, o);
    if (lane == 0) smB[wid] = sum;
    __syncthreads();
    if (tid < 8) {
        float x = smB[tid];
#pragma unroll
        for (int o = 4; o; o >>= 1) x += __shfl_xor_sync(0xffu, x, o);
        if (tid == 0) smB[8] = x;
    }
    __syncthreads();
    sum = smB[8];

    float inv = 1.f / sum;
#pragma unroll
    for (int i = 0; i < 4; i++) p[tid + i * 256] = v[i] * inv;
}

// ----------------------------------------------------------------------------
// Sequential heavy-hitter eviction scan (R1-proven)
// ----------------------------------------------------------------------------
__global__ void __launch_bounds__(1024) scan_kernel(const float* __restrict__ P,
                                                    int* __restrict__ evict)
{
    const int z = blockIdx.x;
    const float* Pz = P + (long long)z * Sc * Sc;
    const int j = threadIdx.x;
    const int lane = j & 31, wid = j >> 5;

    __shared__ float wcoef[CBc];
    __shared__ float sred[33];
    __shared__ unsigned long long mred[33];

    if (j < CBc) wcoef[j] = powf(FFc, (float)(CBc - 1 - j));
    __syncthreads();

    float sel = 0.f;
    for (int i = 0; i < CBc; i++)
        sel += wcoef[i] * Pz[(long long)i * Sc + j];

    const float INFV = __int_as_float(0x7f800000);
    int my_e = 0x7fffffff;

    for (int t = CBc; t <= Sc - 2; t++) {
        float sc = __ldg(&Pz[(long long)t * Sc + j]);
        bool alive = (sel < INFV);
        float cur = alive ? sc : 0.f;

        float x = cur;
#pragma unroll
        for (int o = 16; o; o >>= 1) x += __shfl_xor_sync(0xffffffffu, x, o);
        if (lane == 0) sred[wid] = x;
        __syncthreads();
        if (j < 32) {
            float y = sred[j];
#pragma unroll
            for (int o = 16; o; o >>= 1) y += __shfl_xor_sync(0xffffffffu, y, o);
            if (j == 0) sred[32] = y;
        }
        __syncthreads();
        float total = sred[32];

        sel = alive ? (FFc * sel + cur / total) : INFV;

        unsigned long long key = ~0ull;
        if (j >= SBc && j <= t - RBc)
            key = (((unsigned long long)__float_as_uint(sel)) << 32) | (unsigned)j;
#pragma unroll
        for (int o = 16; o; o >>= 1) {
            unsigned long long other = __shfl_xor_sync(0xffffffffu, key, o);
            key = (other < key) ? other : key;
        }
        if (lane == 0) mred[wid] = key;
        __syncthreads();
        if (j < 32) {
            unsigned long long y = mred[j];
#pragma unroll
            for (int o = 16; o; o >>= 1) {
                unsigned long long other = __shfl_xor_sync(0xffffffffu, y, o);
                y = (other < y) ? other : y;
            }
            if (j == 0) mred[32] = y;
        }
        __syncthreads();
        int mi = (int)(mred[32] & 0xffffffffu);
        if (j == mi) { sel = INFV; my_e = t; }
    }

    evict[z * Sc + j] = my_e;
}

// ----------------------------------------------------------------------------
// Keep-mask + renormalize; emit bf16 hi/lo splits of masked probs
// ----------------------------------------------------------------------------
__global__ void __launch_bounds__(256) maskrenorm_split(const float* __restrict__ P,
                                                        const int* __restrict__ evict,
                                                        __nv_bfloat16* __restrict__ PH,
                                                        __nv_bfloat16* __restrict__ PL)
{
    __shared__ float smB[9];
    long long row = blockIdx.x;
    int z = (int)(row >> 10);
    int r = (int)(row & 1023);
    const float* p = P + row * Sc;
    const int* e = evict + z * Sc;
    const int tid = threadIdx.x;
    const int lane = tid & 31, wid = tid >> 5;

    float v[4];
    float sum = 0.f;
#pragma unroll
    for (int i = 0; i < 4; i++) {
        int jj = tid + i * 256;
        bool keep = (r <= CBc) || (e[jj] >= r);
        v[i] = keep ? p[jj] : 0.f;
        sum += v[i];
    }
#pragma unroll
    for (int o = 16; o; o >>= 1) sum += __shfl_xor_sync(0xffffffffu, sum, o);
    if (lane == 0) smB[wid] = sum;
    __syncthreads();
    if (tid < 8) {
        float x = smB[tid];
#pragma unroll
        for (int o = 4; o; o >>= 1) x += __shfl_xor_sync(0xffu, x, o);
        if (tid == 0) smB[8] = x;
    }
    __syncthreads();
    sum = smB[8];

    float inv = 1.f / sum;
    long long base = row * Sc;
#pragma unroll
    for (int i = 0; i < 4; i++) {
        int jj = tid + i * 256;
        float val = v[i] * inv;
        __nv_bfloat16 h = __float2bfloat16(val);
        PH[base + jj] = h;
        PL[base + jj] = __float2bfloat16(val - __bfloat162float(h));
    }
}

// ----------------------------------------------------------------------------
// Launch
// ----------------------------------------------------------------------------
extern "C" void kernel_launch(void* const* d_in, const int* in_sizes, int n_in,
                              void* d_out, int out_size)
{
    (void)in_sizes; (void)n_in; (void)out_size;
    const float* hs = (const float*)d_in[0];
    const float* wq = (const float*)d_in[1];
    const float* wk = (const float*)d_in[2];
    const float* wv = (const float*)d_in[3];
    const float* wo = (const float*)d_in[4];
    float* out = (float*)d_out;

    float *Qlin, *Klin, *Vlin, *P, *ctx;
    __nv_bfloat16 *hsH, *hsL, *wqH, *wqL, *wkH, *wkL, *wvH, *wvL, *woH, *woL;
    __nv_bfloat16 *QH, *QL, *KH, *KL, *VH, *VL, *PH, *PL, *cH, *cL;
    int* ev;
    cudaGetSymbolAddress((void**)&Qlin, g_Qlin);
    cudaGetSymbolAddress((void**)&Klin, g_Klin);
    cudaGetSymbolAddress((void**)&Vlin, g_Vlin);
    cudaGetSymbolAddress((void**)&hsH, g_hsH);  cudaGetSymbolAddress((void**)&hsL, g_hsL);
    cudaGetSymbolAddress((void**)&wqH, g_wqH);  cudaGetSymbolAddress((void**)&wqL, g_wqL);
    cudaGetSymbolAddress((void**)&wkH, g_wkH);  cudaGetSymbolAddress((void**)&wkL, g_wkL);
    cudaGetSymbolAddress((void**)&wvH, g_wvH);  cudaGetSymbolAddress((void**)&wvL, g_wvL);
    cudaGetSymbolAddress((void**)&woH, g_woH);  cudaGetSymbolAddress((void**)&woL, g_woL);
    cudaGetSymbolAddress((void**)&QH, g_QH);    cudaGetSymbolAddress((void**)&QL, g_QL);
    cudaGetSymbolAddress((void**)&KH, g_KH);    cudaGetSymbolAddress((void**)&KL, g_KL);
    cudaGetSymbolAddress((void**)&VH, g_VH);    cudaGetSymbolAddress((void**)&VL, g_VL);
    cudaGetSymbolAddress((void**)&P, g_P);
    cudaGetSymbolAddress((void**)&PH, g_PH);    cudaGetSymbolAddress((void**)&PL, g_PL);
    cudaGetSymbolAddress((void**)&ctx, g_ctx);
    cudaGetSymbolAddress((void**)&cH, g_cH);    cudaGetSymbolAddress((void**)&cL, g_cL);
    cudaGetSymbolAddress((void**)&ev, g_evict);

    cudaFuncSetAttribute(gemm_mma<true,false>,  cudaFuncAttributeMaxDynamicSharedMemorySize, GSMEM_TOTAL);
    cudaFuncSetAttribute(gemm_mma<false,true>,  cudaFuncAttributeMaxDynamicSharedMemorySize, GSMEM_TOTAL);

    const float qk_scale = 0.08838834764831845f;  // 1/sqrt(128)
    const int NELT = BSc*HIDc;                    // 4M
    const int splitBlocks = NELT/4/256;

    // 1) bf16 hi/lo splits of hs and weights (weights kept [K,N] row-major)
    split_plain<<<splitBlocks, 256>>>(hs, hsH, hsL, NELT);
    split_plain<<<splitBlocks, 256>>>(wq, wqH, wqL, NELT);
    split_plain<<<splitBlocks, 256>>>(wk, wkH, wkL, NELT);
    split_plain<<<splitBlocks, 256>>>(wv, wvH, wvL, NELT);
    split_plain<<<splitBlocks, 256>>>(wo, woH, woL, NELT);

    // 2) QKV projections: A=[2048,2048], B=[K,N] (trans path)
    gemm_mma<true,false><<<dim3(16,16,1), 256, GSMEM_TOTAL>>>(hsH, hsL, wqH, wqL, Qlin,
        HIDc, HIDc, HIDc, 0, 0, 0, 0, 1, 1.f);
    gemm_mma<true,false><<<dim3(16,16,1), 256, GSMEM_TOTAL>>>(hsH, hsL, wkH, wkL, Klin,
        HIDc, HIDc, HIDc, 0, 0, 0, 0, 1, 1.f);
    gemm_mma<true,false><<<dim3(16,16,1), 256, GSMEM_TOTAL>>>(hsH, hsL, wvH, wvL, Vlin,
        HIDc, HIDc, HIDc, 0, 0, 0, 0, 1, 1.f);

    // 3) RoPE + layout + split
    rope_split<<<NELT/256, 256>>>();

    // 4) QK^T causal, scaled: A=Q[z], B=K[z] as [N,K] (non-trans path)
    gemm_mma<false,true><<<dim3(8,8,ZB), 256, GSMEM_TOTAL>>>(QH, QL, KH, KL, P,
        HDc, HDc, Sc,
        (long long)Sc*HDc, (long long)Sc*HDc,
        (long long)Sc*Sc, 0, 1, qk_scale);

    // 5) softmax (causal-aware)
    softmax_causal<<<ZB*Sc, 256>>>(P);

    // 6) eviction scan
    scan_kernel<<<ZB, 1024>>>(P, ev);

    // 7) mask + renormalize -> bf16 splits
    maskrenorm_split<<<ZB*Sc, 256>>>(P, ev, PH, PL);

    // 8) PV: A=P[z] [1024,1024], B=V[z] [K=1024, N=128] (trans path)
    gemm_mma<true,false><<<dim3(1,8,ZB), 256, GSMEM_TOTAL>>>(PH, PL, VH, VL, ctx,
        Sc, HDc, HIDc,
        (long long)Sc*Sc, (long long)Sc*HDc,
        (long long)Sc*HIDc, (long long)HDc, NHc, 1.f);

    // 9) output projection
    split_plain<<<splitBlocks, 256>>>(ctx, cH, cL, NELT);
    gemm_mma<true,false><<<dim3(16,16,1), 256, GSMEM_TOTAL>>>(cH, cL, woH, woL, out,
        HIDc, HIDc, HIDc, 0, 0, 0, 0, 1, 1.f);
}

// round 4
// speedup vs baseline: 2.1271x; 1.2358x over previous
#include <cuda_runtime.h>
#include <cuda_bf16.h>
#include <math.h>
#include <float.h>
#include <stdint.h>

// Problem constants
#define Bc    2
#define Sc    1024
#define HIDc  2048
#define NHc   16
#define HDc   128
#define SBc   20
#define RBc   82
#define CBc   163
#define FFc   0.9f
#define BSc   (Bc*Sc)          // 2048
#define ZB    (Bc*NHc)         // 32

// ----------------------------------------------------------------------------
// Scratch
// ----------------------------------------------------------------------------
__device__ __align__(1024) float g_Qlin[BSc*HIDc];
__device__ __align__(1024) float g_Klin[BSc*HIDc];
__device__ __align__(1024) float g_Vlin[BSc*HIDc];
__device__ __align__(1024) __nv_bfloat16 g_hsH[BSc*HIDc];
__device__ __align__(1024) __nv_bfloat16 g_hsL[BSc*HIDc];
__device__ __align__(1024) __nv_bfloat16 g_wqH[HIDc*HIDc];
__device__ __align__(1024) __nv_bfloat16 g_wqL[HIDc*HIDc];
__device__ __align__(1024) __nv_bfloat16 g_wkH[HIDc*HIDc];
__device__ __align__(1024) __nv_bfloat16 g_wkL[HIDc*HIDc];
__device__ __align__(1024) __nv_bfloat16 g_wvH[HIDc*HIDc];
__device__ __align__(1024) __nv_bfloat16 g_wvL[HIDc*HIDc];
__device__ __align__(1024) __nv_bfloat16 g_woH[HIDc*HIDc];
__device__ __align__(1024) __nv_bfloat16 g_woL[HIDc*HIDc];
__device__ __align__(1024) __nv_bfloat16 g_QH[ZB*Sc*HDc];
__device__ __align__(1024) __nv_bfloat16 g_QL[ZB*Sc*HDc];
__device__ __align__(1024) __nv_bfloat16 g_KH[ZB*Sc*HDc];
__device__ __align__(1024) __nv_bfloat16 g_KL[ZB*Sc*HDc];
__device__ __align__(1024) __nv_bfloat16 g_VH[ZB*Sc*HDc];
__device__ __align__(1024) __nv_bfloat16 g_VL[ZB*Sc*HDc];
__device__ __align__(1024) float g_P[(size_t)ZB*Sc*Sc];
__device__ __align__(1024) __nv_bfloat16 g_PH[(size_t)ZB*Sc*Sc];
__device__ __align__(1024) __nv_bfloat16 g_PL[(size_t)ZB*Sc*Sc];
__device__ __align__(1024) __nv_bfloat16 g_cH[BSc*HIDc];
__device__ __align__(1024) __nv_bfloat16 g_cL[BSc*HIDc];
__device__ int g_evict[ZB*Sc];
__device__ float g_tcos[Sc*64];
__device__ float g_tsin[Sc*64];

// ----------------------------------------------------------------------------
// PTX helpers (baseline PTX only: cp.async, ldmatrix, mma.sync — all sm_80+)
// ----------------------------------------------------------------------------
__device__ __forceinline__ uint32_t smem_u32(const void* p){
    uint32_t a;
    asm("{ .reg .u64 t; cvta.to.shared.u64 t, %1; cvt.u32.u64 %0, t; }":"=r"(a):"l"(p));
    return a;
}
__device__ __forceinline__ void cp16(uint32_t d, const void* s){
    asm volatile("cp.async.cg.shared.global [%0], [%1], 16;"::"r"(d),"l"(s));
}
#define CP_COMMIT() asm volatile("cp.async.commit_group;":::"memory")
#define CP_WAIT(n)  asm volatile("cp.async.wait_group %0;"::"n"(n):"memory")

__device__ __forceinline__ void ldsm4(uint32_t r[4], uint32_t a){
    asm volatile("ldmatrix.sync.aligned.m8n8.x4.shared.b16 {%0,%1,%2,%3}, [%4];"
        : "=r"(r[0]),"=r"(r[1]),"=r"(r[2]),"=r"(r[3]) : "r"(a));
}
__device__ __forceinline__ void ldsm4t(uint32_t r[4], uint32_t a){
    asm volatile("ldmatrix.sync.aligned.m8n8.x4.trans.shared.b16 {%0,%1,%2,%3}, [%4];"
        : "=r"(r[0]),"=r"(r[1]),"=r"(r[2]),"=r"(r[3]) : "r"(a));
}
__device__ __forceinline__ void mma16816(float d[4], const uint32_t a[4], const uint32_t b[2]){
    asm volatile("mma.sync.aligned.m16n8k16.row.col.f32.bf16.bf16.f32 "
        "{%0,%1,%2,%3},{%4,%5,%6,%7},{%8,%9},{%0,%1,%2,%3};"
        : "+f"(d[0]),"+f"(d[1]),"+f"(d[2]),"+f"(d[3])
        : "r"(a[0]),"r"(a[1]),"r"(a[2]),"r"(a[3]),"r"(b[0]),"r"(b[1]));
}

#define TILEB       16384
#define STAGE_BYTES 65536
#define NSTAGE      3
#define GSMEM_TOTAL (NSTAGE*STAGE_BYTES)   // 192 KB

// Copy a [128 rows x 64 bf16] tile, rowbytes=128, XOR-(r&7) chunk swizzle.
__device__ __forceinline__ void copy_rk(uint32_t dst, const __nv_bfloat16* src,
                                        int ld, int tid){
#pragma unroll
    for (int i=0;i<4;i++){
        int idx = tid + i*256;
        int r = idx>>3, c = idx&7;
        uint32_t sw = (uint32_t)(r*128) + (uint32_t)(((c ^ (r&7))<<4));
        cp16(dst + sw, (const char*)src + ((long long)r*ld + c*8)*2);
    }
}
// Copy a [64 rows(k) x 128 bf16(n)] tile, rowbytes=256, XOR-(r&7) chunk swizzle.
__device__ __forceinline__ void copy_kn(uint32_t dst, const __nv_bfloat16* src,
                                        int ld, int tid){
#pragma unroll
    for (int i=0;i<4;i++){
        int idx = tid + i*256;
        int r = idx>>4, c = idx&15;
        uint32_t sw = (uint32_t)(r*256) + (uint32_t)(((c ^ (r&7))<<4));
        cp16(dst + sw, (const char*)src + ((long long)r*ld + c*8)*2);
    }
}

// ----------------------------------------------------------------------------
// HMMA GEMM: C[M,N] = alpha * (Ah+Al)[M,K] @ (Bh+Bl)^T, fp32 C, 3-term split.
// BKN=true : B stored [K,N] row-major (trans ldmatrix)
// BKN=false: B stored [N,K] row-major
// CAUSAL: skip 128x128 blocks strictly above the diagonal.
// SPLITOUT: write bf16 hi/lo (CH/CL) instead of fp32 C.
// CTA 128x128, 8 warps (2x4 of 64x32), K-chunk 64, 3-stage cp.async pipeline.
// ----------------------------------------------------------------------------
template<bool BKN, bool CAUSAL, bool SPLITOUT>
__global__ void __launch_bounds__(256) gemm_mma(
    const __nv_bfloat16* __restrict__ Ah, const __nv_bfloat16* __restrict__ Al,
    const __nv_bfloat16* __restrict__ Bh, const __nv_bfloat16* __restrict__ Bl,
    float* __restrict__ C,
    __nv_bfloat16* __restrict__ CH, __nv_bfloat16* __restrict__ CL,
    int K, int ldb, int ldc,
    long long sA, long long sB, long long sCo, long long sCi, int ndiv, float alpha)
{
    const int m0 = blockIdx.y*128, n0 = blockIdx.x*128, z = blockIdx.z;
    if (CAUSAL && n0 > m0) return;
    extern __shared__ __align__(1024) char smem[];
    const uint32_t sb = smem_u32(smem);
    Ah += (long long)z*sA; Al += (long long)z*sA;
    Bh += (long long)z*sB; Bl += (long long)z*sB;
    long long coff = (long long)(z/ndiv)*sCo + (long long)(z%ndiv)*sCi;
    if (SPLITOUT){ CH += coff; CL += coff; } else { C += coff; }

    const int tid = threadIdx.x, lane = tid&31, wid = tid>>5;
    const int wm = wid>>2, wn = wid&3;

    float acc[4][4][4];
#pragma unroll
    for (int a=0;a<4;a++)
#pragma unroll
        for (int b=0;b<4;b++)
#pragma unroll
            for (int c=0;c<4;c++) acc[a][b][c] = 0.f;

    const int nch = K>>6;

#define LOAD_CHUNK(cc, ss) do{ \
    uint32_t bbase = sb + (uint32_t)(ss)*STAGE_BYTES; \
    copy_rk(bbase,           Ah + (long long)m0*K + (cc)*64, K, tid); \
    copy_rk(bbase + TILEB,   Al + (long long)m0*K + (cc)*64, K, tid); \
    if (BKN){ \
        copy_kn(bbase + 2*TILEB, Bh + (long long)(cc)*64*ldb + n0, ldb, tid); \
        copy_kn(bbase + 3*TILEB, Bl + (long long)(cc)*64*ldb + n0, ldb, tid); \
    } else { \
        copy_rk(bbase + 2*TILEB, Bh + (long long)n0*K + (cc)*64, K, tid); \
        copy_rk(bbase + 3*TILEB, Bl + (long long)n0*K + (cc)*64, K, tid); \
    } \
    CP_COMMIT(); }while(0)

    LOAD_CHUNK(0, 0);
    if (nch > 1) LOAD_CHUNK(1, 1);
    if (nch > 2) LOAD_CHUNK(2, 2);

    const uint32_t axor = (uint32_t)(lane&7);

    for (int c=0; c<nch; c++){
        int pend = nch-1-c; if (pend > 2) pend = 2;
        if (pend == 2) CP_WAIT(2);
        else if (pend == 1) CP_WAIT(1);
        else CP_WAIT(0);
        __syncthreads();
        uint32_t base = sb + (uint32_t)(c % NSTAGE)*STAGE_BYTES;
#pragma unroll
        for (int ks=0; ks<4; ks++){
            uint32_t ah[4][4], al[4][4], bh[4][2], bl[4][2];
#pragma unroll
            for (int mb=0;mb<4;mb++){
                uint32_t row = (uint32_t)(wm*64 + mb*16 + (lane&15));
                uint32_t col = (((uint32_t)(ks*2 + (lane>>4)) ^ axor)<<4);
                uint32_t ad = base + row*128 + col;
                ldsm4(ah[mb], ad);
                ldsm4(al[mb], ad + TILEB);
            }
#pragma unroll
            for (int nb=0;nb<2;nb++){
                uint32_t t[4];
                if (BKN){
                    uint32_t row = (uint32_t)(ks*16 + (lane&7) + (((lane>>3)&1)<<3));
                    uint32_t ch  = ((uint32_t)(wn*4 + nb*2 + (lane>>4)) ^ axor);
                    uint32_t ad  = base + 2*TILEB + row*256 + (ch<<4);
                    ldsm4t(t, ad);
                    bh[2*nb][0]=t[0]; bh[2*nb][1]=t[1]; bh[2*nb+1][0]=t[2]; bh[2*nb+1][1]=t[3];
                    ldsm4t(t, ad + TILEB);
                    bl[2*nb][0]=t[0]; bl[2*nb][1]=t[1]; bl[2*nb+1][0]=t[2]; bl[2*nb+1][1]=t[3];
                } else {
                    uint32_t row = (uint32_t)(wn*32 + nb*16 + (lane&7) + ((lane>>4)<<3));
                    uint32_t ch  = ((uint32_t)(ks*2 + ((lane>>3)&1)) ^ axor);
                    uint32_t ad  = base + 2*TILEB + row*128 + (ch<<4);
                    ldsm4(t, ad);
                    bh[2*nb][0]=t[0]; bh[2*nb][1]=t[1]; bh[2*nb+1][0]=t[2]; bh[2*nb+1][1]=t[3];
                    ldsm4(t, ad + TILEB);
                    bl[2*nb][0]=t[0]; bl[2*nb][1]=t[1]; bl[2*nb+1][0]=t[2]; bl[2*nb+1][1]=t[3];
                }
            }
#pragma unroll
            for (int mb=0;mb<4;mb++)
#pragma unroll
                for (int n8=0;n8<4;n8++){
                    mma16816(acc[mb][n8], ah[mb], bh[n8]);
                    mma16816(acc[mb][n8], ah[mb], bl[n8]);
                    mma16816(acc[mb][n8], al[mb], bh[n8]);
                }
        }
        __syncthreads();
        if (c + NSTAGE < nch) LOAD_CHUNK(c + NSTAGE, c % NSTAGE);
    }
#undef LOAD_CHUNK

    // epilogue
#pragma unroll
    for (int mb=0;mb<4;mb++){
        int r0 = m0 + wm*64 + mb*16 + (lane>>2);
#pragma unroll
        for (int n8=0;n8<4;n8++){
            int cc = n0 + wn*32 + n8*8 + (lane&3)*2;
            float vx0 = acc[mb][n8][0]*alpha, vy0 = acc[mb][n8][1]*alpha;
            float vx1 = acc[mb][n8][2]*alpha, vy1 = acc[mb][n8][3]*alpha;
            if (SPLITOUT){
                __nv_bfloat162 h0, l0, h1, l1;
                h0.x = __float2bfloat16(vx0); h0.y = __float2bfloat16(vy0);
                l0.x = __float2bfloat16(vx0 - __bfloat162float(h0.x));
                l0.y = __float2bfloat16(vy0 - __bfloat162float(h0.y));
                h1.x = __float2bfloat16(vx1); h1.y = __float2bfloat16(vy1);
                l1.x = __float2bfloat16(vx1 - __bfloat162float(h1.x));
                l1.y = __float2bfloat16(vy1 - __bfloat162float(h1.y));
                *(__nv_bfloat162*)&CH[(long long)r0*ldc + cc] = h0;
                *(__nv_bfloat162*)&CL[(long long)r0*ldc + cc] = l0;
                *(__nv_bfloat162*)&CH[(long long)(r0+8)*ldc + cc] = h1;
                *(__nv_bfloat162*)&CL[(long long)(r0+8)*ldc + cc] = l1;
            } else {
                float2 v0; v0.x = vx0; v0.y = vy0;
                float2 v1; v1.x = vx1; v1.y = vy1;
                *(float2*)&C[(long long)r0*ldc + cc] = v0;
                *(float2*)&C[(long long)(r0+8)*ldc + cc] = v1;
            }
        }
    }
}

// ----------------------------------------------------------------------------
// fp32 -> bf16 hi/lo split (same layout), 4 elems/thread
// ----------------------------------------------------------------------------
__global__ void split_plain(const float* __restrict__ X,
                            __nv_bfloat16* __restrict__ H,
                            __nv_bfloat16* __restrict__ L, int n)
{
    int i = (blockIdx.x*blockDim.x + threadIdx.x)*4;
    if (i < n){
        float4 v = *(const float4*)&X[i];
        __nv_bfloat16 h0=__float2bfloat16(v.x), h1=__float2bfloat16(v.y);
        __nv_bfloat16 h2=__float2bfloat16(v.z), h3=__float2bfloat16(v.w);
        __nv_bfloat162 H01; H01.x=h0; H01.y=h1;
        __nv_bfloat162 H23; H23.x=h2; H23.y=h3;
        *(__nv_bfloat162*)&H[i]   = H01;
        *(__nv_bfloat162*)&H[i+2] = H23;
        __nv_bfloat162 L01, L23;
        L01.x = __float2bfloat16(v.x - __bfloat162float(h0));
        L01.y = __float2bfloat16(v.y - __bfloat162float(h1));
        L23.x = __float2bfloat16(v.z - __bfloat162float(h2));
        L23.y = __float2bfloat16(v.w - __bfloat162float(h3));
        *(__nv_bfloat162*)&L[i]   = L01;
        *(__nv_bfloat162*)&L[i+2] = L23;
    }
}

// ----------------------------------------------------------------------------
// RoPE cos/sin tables (fp64-accurate, computed once per launch; cheap)
// ----------------------------------------------------------------------------
__global__ void rope_tables()
{
    int idx = blockIdx.x*blockDim.x + threadIdx.x;   // 0 .. Sc*64-1
    int s = idx >> 6, i = idx & 63;
    double inv = pow(10000.0, -(double)i/64.0);
    double a = (double)s * inv;
    g_tcos[idx] = (float)cos(a);
    g_tsin[idx] = (float)sin(a);
}

// ----------------------------------------------------------------------------
// RoPE + [B,S,H*D]->[Z,S,D] layout + bf16 hi/lo split (table-driven)
// ----------------------------------------------------------------------------
__global__ void rope_split()
{
    long long idx = (long long)blockIdx.x * blockDim.x + threadIdx.x;
    if (idx >= (long long)Bc * Sc * HIDc) return;

    int d = (int)(idx % HDc);
    int h = (int)((idx / HDc) % NHc);
    int s = (int)((idx / HIDc) % Sc);
    int b = (int)(idx / ((long long)Sc * HIDc));
    int z = b*NHc + h;

    long long lin = (long long)(b * Sc + s) * HIDc + h * HDc + d;
    long long out = (long long)(z * Sc + s) * HDc + d;

    float q = g_Qlin[lin];
    float k = g_Klin[lin];
    float qr, kr;
    if (d < 64) { qr = -g_Qlin[lin + 64]; kr = -g_Klin[lin + 64]; }
    else        { qr =  g_Qlin[lin - 64]; kr =  g_Klin[lin - 64]; }

    int ti = (s<<6) + (d & 63);
    float c = g_tcos[ti], sn = g_tsin[ti];

    float qv = q * c + qr * sn;
    float kv = k * c + kr * sn;

    __nv_bfloat16 qh = __float2bfloat16(qv);
    g_QH[out] = qh; g_QL[out] = __float2bfloat16(qv - __bfloat162float(qh));
    __nv_bfloat16 kh = __float2bfloat16(kv);
    g_KH[out] = kh; g_KL[out] = __float2bfloat16(kv - __bfloat162float(kh));

    float vv = g_Vlin[lin];
    __nv_bfloat16 vh = __float2bfloat16(vv);
    g_VH[out] = vh; g_VL[out] = __float2bfloat16(vv - __bfloat162float(vh));
}

// ----------------------------------------------------------------------------
// Causal row softmax: row r uses j<=r; writes 0 above the diagonal
// ----------------------------------------------------------------------------
__global__ void __launch_bounds__(256) softmax_causal(float* __restrict__ P)
{
    __shared__ float smA[9];
    __shared__ float smB[9];
    long long row = blockIdx.x;
    int r = (int)(row & (Sc-1));
    float* p = P + row * Sc;
    const int tid = threadIdx.x;
    const int lane = tid & 31, wid = tid >> 5;

    float v[4];
    float mx = -FLT_MAX;
#pragma unroll
    for (int i = 0; i < 4; i++) {
        int jj = tid + i*256;
        v[i] = (jj <= r) ? p[jj] : -FLT_MAX;
        mx = fmaxf(mx, v[i]);
    }
#pragma unroll
    for (int o = 16; o; o >>= 1) mx = fmaxf(mx, __shfl_xor_sync(0xffffffffu, mx, o));
    if (lane == 0) smA[wid] = mx;
    __syncthreads();
    if (tid < 8) {
        float x = smA[tid];
#pragma unroll
        for (int o = 4; o; o >>= 1) x = fmaxf(x, __shfl_xor_sync(0xffu, x, o));
        if (tid == 0) smA[8] = x;
    }
    __syncthreads();
    mx = smA[8];

    float sum = 0.f;
#pragma unroll
    for (int i = 0; i < 4; i++) { v[i] = expf(v[i] - mx); sum += v[i]; }
#pragma unroll
    for (int o = 16; o; o >>= 1) sum += __shfl_xor_sync(0xffffffffu, sum, o);
    if (lane == 0) smB[wid] = sum;
    __syncthreads();
    if (tid < 8) {
        float x = smB[tid];
#pragma unroll
        for (int o = 4; o; o >>= 1) x += __shfl_xor_sync(0xffu, x, o);
        if (tid == 0) smB[8] = x;
    }
    __syncthreads();
    sum = smB[8];

    float inv = 1.f / sum;
#pragma unroll
    for (int i = 0; i < 4; i++) p[tid + i * 256] = v[i] * inv;
}

// ----------------------------------------------------------------------------
// Sequential heavy-hitter eviction scan.
// 2 barriers/step (redundant per-warp final reduction) + next-row prefetch.
// ----------------------------------------------------------------------------
__global__ void __launch_bounds__(1024) scan_kernel(const float* __restrict__ P,
                                                    int* __restrict__ evict)
{
    const int z = blockIdx.x;
    const float* Pz = P + (long long)z * Sc * Sc;
    const int j = threadIdx.x;
    const int lane = j & 31, wid = j >> 5;

    __shared__ float wcoef[CBc];
    __shared__ float sred[32];
    __shared__ unsigned long long mred[32];

    if (j < CBc) wcoef[j] = powf(FFc, (float)(CBc - 1 - j));
    __syncthreads();

    float sel = 0.f;
    for (int i = 0; i < CBc; i++)
        sel += wcoef[i] * Pz[(long long)i * Sc + j];

    const float INFV = __int_as_float(0x7f800000);
    int my_e = 0x7fffffff;

    float sc = __ldg(&Pz[(long long)CBc * Sc + j]);

    for (int t = CBc; t <= Sc - 2; t++) {
        float nxt = 0.f;
        if (t < Sc - 2) nxt = __ldg(&Pz[(long long)(t+1) * Sc + j]);

        bool alive = (sel < INFV);
        float cur = alive ? sc : 0.f;

        // block sum of cur (1 barrier; every warp redundantly reduces warp sums)
        float x = cur;
#pragma unroll
        for (int o = 16; o; o >>= 1) x += __shfl_xor_sync(0xffffffffu, x, o);
        if (lane == 0) sred[wid] = x;
        __syncthreads();
        float y = sred[lane];
#pragma unroll
        for (int o = 16; o; o >>= 1) y += __shfl_xor_sync(0xffffffffu, y, o);
        float total = y;

        sel = alive ? (FFc * sel + cur / total) : INFV;

        // windowed argmin (first index on ties) — 1 barrier
        unsigned long long key = ~0ull;
        if (j >= SBc && j <= t - RBc)
            key = (((unsigned long long)__float_as_uint(sel)) << 32) | (unsigned)j;
#pragma unroll
        for (int o = 16; o; o >>= 1) {
            unsigned long long other = __shfl_xor_sync(0xffffffffu, key, o);
            key = (other < key) ? other : key;
        }
        if (lane == 0) mred[wid] = key;
        __syncthreads();
        unsigned long long y2 = mred[lane];
#pragma unroll
        for (int o = 16; o; o >>= 1) {
            unsigned long long other = __shfl_xor_sync(0xffffffffu, y2, o);
            y2 = (other < y2) ? other : y2;
        }
        int mi = (int)(y2 & 0xffffffffu);
        if (j == mi) { sel = INFV; my_e = t; }

        sc = nxt;
    }

    evict[z * Sc + j] = my_e;
}

// ----------------------------------------------------------------------------
// Keep-mask + renormalize; emit bf16 hi/lo splits of masked probs
// ----------------------------------------------------------------------------
__global__ void __launch_bounds__(256) maskrenorm_split(const float* __restrict__ P,
                                                        const int* __restrict__ evict,
                                                        __nv_bfloat16* __restrict__ PH,
                                                        __nv_bfloat16* __restrict__ PL)
{
    __shared__ float smB[9];
    long long row = blockIdx.x;
    int z = (int)(row >> 10);
    int r = (int)(row & 1023);
    const float* p = P + row * Sc;
    const int* e = evict + z * Sc;
    const int tid = threadIdx.x;
    const int lane = tid & 31, wid = tid >> 5;

    float v[4];
    float sum = 0.f;
#pragma unroll
    for (int i = 0; i < 4; i++) {
        int jj = tid + i * 256;
        bool keep = (r <= CBc) || (e[jj] >= r);
        v[i] = keep ? p[jj] : 0.f;
        sum += v[i];
    }
#pragma unroll
    for (int o = 16; o; o >>= 1) sum += __shfl_xor_sync(0xffffffffu, sum, o);
    if (lane == 0) smB[wid] = sum;
    __syncthreads();
    if (tid < 8) {
        float x = smB[tid];
#pragma unroll
        for (int o = 4; o; o >>= 1) x += __shfl_xor_sync(0xffu, x, o);
        if (tid == 0) smB[8] = x;
    }
    __syncthreads();
    sum = smB[8];

    float inv = 1.f / sum;
    long long base = row * Sc;
#pragma unroll
    for (int i = 0; i < 4; i++) {
        int jj = tid + i * 256;
        float val = v[i] * inv;
        __nv_bfloat16 h = __float2bfloat16(val);
        PH[base + jj] = h;
        PL[base + jj] = __float2bfloat16(val - __bfloat162float(h));
    }
}

// ----------------------------------------------------------------------------
// Launch
// ----------------------------------------------------------------------------
extern "C" void kernel_launch(void* const* d_in, const int* in_sizes, int n_in,
                              void* d_out, int out_size)
{
    (void)in_sizes; (void)n_in; (void)out_size;
    const float* hs = (const float*)d_in[0];
    const float* wq = (const float*)d_in[1];
    const float* wk = (const float*)d_in[2];
    const float* wv = (const float*)d_in[3];
    const float* wo = (const float*)d_in[4];
    float* out = (float*)d_out;

    float *Qlin, *Klin, *Vlin, *P;
    __nv_bfloat16 *hsH, *hsL, *wqH, *wqL, *wkH, *wkL, *wvH, *wvL, *woH, *woL;
    __nv_bfloat16 *QH, *QL, *KH, *KL, *VH, *VL, *PH, *PL, *cH, *cL;
    int* ev;
    cudaGetSymbolAddress((void**)&Qlin, g_Qlin);
    cudaGetSymbolAddress((void**)&Klin, g_Klin);
    cudaGetSymbolAddress((void**)&Vlin, g_Vlin);
    cudaGetSymbolAddress((void**)&hsH, g_hsH);  cudaGetSymbolAddress((void**)&hsL, g_hsL);
    cudaGetSymbolAddress((void**)&wqH, g_wqH);  cudaGetSymbolAddress((void**)&wqL, g_wqL);
    cudaGetSymbolAddress((void**)&wkH, g_wkH);  cudaGetSymbolAddress((void**)&wkL, g_wkL);
    cudaGetSymbolAddress((void**)&wvH, g_wvH);  cudaGetSymbolAddress((void**)&wvL, g_wvL);
    cudaGetSymbolAddress((void**)&woH, g_woH);  cudaGetSymbolAddress((void**)&woL, g_woL);
    cudaGetSymbolAddress((void**)&QH, g_QH);    cudaGetSymbolAddress((void**)&QL, g_QL);
    cudaGetSymbolAddress((void**)&KH, g_KH);    cudaGetSymbolAddress((void**)&KL, g_KL);
    cudaGetSymbolAddress((void**)&VH, g_VH);    cudaGetSymbolAddress((void**)&VL, g_VL);
    cudaGetSymbolAddress((void**)&P, g_P);
    cudaGetSymbolAddress((void**)&PH, g_PH);    cudaGetSymbolAddress((void**)&PL, g_PL);
    cudaGetSymbolAddress((void**)&cH, g_cH);    cudaGetSymbolAddress((void**)&cL, g_cL);
    cudaGetSymbolAddress((void**)&ev, g_evict);

    cudaFuncSetAttribute(gemm_mma<true,false,false>,  cudaFuncAttributeMaxDynamicSharedMemorySize, GSMEM_TOTAL);
    cudaFuncSetAttribute(gemm_mma<false,true,false>,  cudaFuncAttributeMaxDynamicSharedMemorySize, GSMEM_TOTAL);
    cudaFuncSetAttribute(gemm_mma<true,false,true>,   cudaFuncAttributeMaxDynamicSharedMemorySize, GSMEM_TOTAL);

    const float qk_scale = 0.08838834764831845f;  // 1/sqrt(128)
    const int NELT = BSc*HIDc;                    // 4M
    const int splitBlocks = NELT/4/256;

    // 0) RoPE tables (cheap, deterministic)
    rope_tables<<<(Sc*64)/256, 256>>>();

    // 1) bf16 hi/lo splits of hs and weights (weights kept [K,N] row-major)
    split_plain<<<splitBlocks, 256>>>(hs, hsH, hsL, NELT);
    split_plain<<<splitBlocks, 256>>>(wq, wqH, wqL, NELT);
    split_plain<<<splitBlocks, 256>>>(wk, wkH, wkL, NELT);
    split_plain<<<splitBlocks, 256>>>(wv, wvH, wvL, NELT);
    split_plain<<<splitBlocks, 256>>>(wo, woH, woL, NELT);

    // 2) QKV projections: A=[2048,2048], B=[K,N] (trans path)
    gemm_mma<true,false,false><<<dim3(16,16,1), 256, GSMEM_TOTAL>>>(hsH, hsL, wqH, wqL, Qlin,
        nullptr, nullptr, HIDc, HIDc, HIDc, 0, 0, 0, 0, 1, 1.f);
    gemm_mma<true,false,false><<<dim3(16,16,1), 256, GSMEM_TOTAL>>>(hsH, hsL, wkH, wkL, Klin,
        nullptr, nullptr, HIDc, HIDc, HIDc, 0, 0, 0, 0, 1, 1.f);
    gemm_mma<true,false,false><<<dim3(16,16,1), 256, GSMEM_TOTAL>>>(hsH, hsL, wvH, wvL, Vlin,
        nullptr, nullptr, HIDc, HIDc, HIDc, 0, 0, 0, 0, 1, 1.f);

    // 3) RoPE + layout + split
    rope_split<<<NELT/256, 256>>>();

    // 4) QK^T causal, scaled: A=Q[z], B=K[z] as [N,K] (non-trans path)
    gemm_mma<false,true,false><<<dim3(8,8,ZB), 256, GSMEM_TOTAL>>>(QH, QL, KH, KL, P,
        nullptr, nullptr, HDc, HDc, Sc,
        (long long)Sc*HDc, (long long)Sc*HDc,
        (long long)Sc*Sc, 0, 1, qk_scale);

    // 5) softmax (causal-aware)
    softmax_causal<<<ZB*Sc, 256>>>(P);

    // 6) eviction scan
    scan_kernel<<<ZB, 1024>>>(P, ev);

    // 7) mask + renormalize -> bf16 splits
    maskrenorm_split<<<ZB*Sc, 256>>>(P, ev, PH, PL);

    // 8) PV: A=P[z] [1024,1024], B=V[z] [K=1024, N=128] (trans path),
    //    write ctx directly as bf16 hi/lo splits
    gemm_mma<true,false,true><<<dim3(1,8,ZB), 256, GSMEM_TOTAL>>>(PH, PL, VH, VL,
        nullptr, cH, cL, Sc, HDc, HIDc,
        (long long)Sc*Sc, (long long)Sc*HDc,
        (long long)Sc*HIDc, (long long)HDc, NHc, 1.f);

    // 9) output projection
    gemm_mma<true,false,false><<<dim3(16,16,1), 256, GSMEM_TOTAL>>>(cH, cL, woH, woL, out,
        nullptr, nullptr, HIDc, HIDc, HIDc, 0, 0, 0, 0, 1, 1.f);
}